// round 9
// baseline (speedup 1.0000x reference)
#include <cuda_runtime.h>
#include <cstdint>

// YOLOv1 loss, S=14, B=2, C=20, BATCH=4096.
// Kernel 1: per-block cp.async.bulk stage (30 KB) -> compute -> partial float.
// Kernel 2 (wide, latency-optimized): sum 6272 partials in double -> scalar.

constexpr int NCH        = 30;              // 5*B + C
constexpr int NB         = 2;
constexpr int CPB        = 128;             // cells per block (one per thread)
constexpr int THREADS    = 128;
constexpr int TILE_FLTS  = CPB * NCH;       // 3840
constexpr int TILE_BYTES = TILE_FLTS * 4;   // 15360 (16B multiple)
constexpr int NBLOCKS    = 4096 * 14 * 14 / CPB;  // 6272
constexpr int NPART4     = NBLOCKS / 4;     // 1568 float4
constexpr int FIN_THREADS = 1024;

__device__ alignas(16) float g_part[NBLOCKS];

__device__ __forceinline__ uint32_t smem_u32(const void* p) {
    return (uint32_t)__cvta_generic_to_shared(p);
}

__global__ void __launch_bounds__(THREADS, 7) yolo_k(
    const float* __restrict__ pred, const float* __restrict__ targ)
{
    __shared__ alignas(16) float sp[TILE_FLTS];
    __shared__ alignas(16) float st_[TILE_FLTS];
    __shared__ alignas(8)  uint64_t mbar;

    const int tid = threadIdx.x;
    const size_t base = (size_t)blockIdx.x * TILE_FLTS;
    const uint32_t mb = smem_u32(&mbar);

    if (tid == 0) {
        asm volatile("mbarrier.init.shared.b64 [%0], 1;" :: "r"(mb) : "memory");
    }
    __syncthreads();

    if (tid == 0) {
        asm volatile("mbarrier.arrive.expect_tx.shared.b64 _, [%0], %1;"
                     :: "r"(mb), "r"(2u * TILE_BYTES) : "memory");
        asm volatile(
            "cp.async.bulk.shared::cta.global.mbarrier::complete_tx::bytes "
            "[%0], [%1], %2, [%3];"
            :: "r"(smem_u32(sp)), "l"(pred + base), "r"((uint32_t)TILE_BYTES),
               "r"(mb) : "memory");
        asm volatile(
            "cp.async.bulk.shared::cta.global.mbarrier::complete_tx::bytes "
            "[%0], [%1], %2, [%3];"
            :: "r"(smem_u32(st_)), "l"(targ + base), "r"((uint32_t)TILE_BYTES),
               "r"(mb) : "memory");
    }

    // Wait for both bulk copies (phase parity 0; block runs one phase only).
    {
        asm volatile(
            "{\n\t"
            ".reg .pred P1;\n\t"
            "WAIT_LOOP_%=:\n\t"
            "mbarrier.try_wait.parity.acquire.cta.shared::cta.b64 P1, [%0], 0, 0x989680;\n\t"
            "@P1 bra.uni WAIT_DONE_%=;\n\t"
            "bra.uni WAIT_LOOP_%=;\n\t"
            "WAIT_DONE_%=:\n\t"
            "}"
            :: "r"(mb) : "memory");
    }

    const float* P = sp  + tid * NCH;
    const float* T = st_ + tid * NCH;

    const float invS = 1.0f / 14.0f;

    const float tobj = T[4];
    const float of = (tobj > 0.0f) ? 1.0f : 0.0f;
    const float nf = 1.0f - of;

    // Target box (box 0 of the tiled pair), in xyxy.
    const float tx0 = T[0] * invS - 0.5f * T[2];
    const float ty0 = T[1] * invS - 0.5f * T[3];
    const float tx1 = T[0] * invS + 0.5f * T[2];
    const float ty1 = T[1] * invS + 0.5f * T[3];
    const float area_t = (tx1 - tx0) * (ty1 - ty0);

    float iou[NB];
    #pragma unroll
    for (int b = 0; b < NB; ++b) {
        const float* Pb = P + 5 * b;
        const float px0 = Pb[0] * invS - 0.5f * Pb[2];
        const float py0 = Pb[1] * invS - 0.5f * Pb[3];
        const float px1 = Pb[0] * invS + 0.5f * Pb[2];
        const float py1 = Pb[1] * invS + 0.5f * Pb[3];
        const float ltx = fmaxf(px0, tx0), lty = fmaxf(py0, ty0);
        const float rbx = fminf(px1, tx1), rby = fminf(py1, ty1);
        const float wx = fmaxf(rbx - ltx, 0.0f);
        const float wy = fmaxf(rby - lty, 0.0f);
        const float inter = wx * wy;
        const float area_p = (px1 - px0) * (py1 - py0);
        iou[b] = inter / (area_p + area_t - inter);  // area_p>0 always
    }
    // jnp.argmax takes the FIRST max -> idx=1 only on strict greater.
    const int idx = (iou[1] > iou[0]) ? 1 : 0;
    const float max_iou = fmaxf(iou[0], iou[1]);

    float lxy = 0.0f, lwh = 0.0f, lobj = 0.0f, lnoobj = 0.0f;
    #pragma unroll
    for (int b = 0; b < NB; ++b) {
        const float* Pb = P + 5 * b;
        const float* Tb = T + 5 * b;
        const bool resp = (of > 0.0f) && (idx == b);
        const float rf = resp ? 1.0f : 0.0f;

        const float dx = Pb[0] - Tb[0];
        const float dy = Pb[1] - Tb[1];
        lxy += rf * (dx * dx + dy * dy);

        const float pw = resp ? Pb[2] : 1.0f;
        const float tw = resp ? Tb[2] : 1.0f;
        const float ph = resp ? Pb[3] : 1.0f;
        const float th = resp ? Tb[3] : 1.0f;
        const float dw = sqrtf(pw) - sqrtf(tw);
        const float dh = sqrtf(ph) - sqrtf(th);
        lwh += rf * (dw * dw + dh * dh);

        const float dob = Pb[4] - max_iou;
        lobj += rf * dob * dob;

        const float dn = Pb[4] - Tb[4];
        lnoobj += dn * dn;
    }
    lnoobj *= nf;

    float lcls = 0.0f;
    #pragma unroll
    for (int k = 10; k < 30; ++k) {
        const float d = P[k] - T[k];
        lcls += d * d;
    }
    lcls *= of;

    float v = 5.0f * (lxy + lwh) + lobj + 0.5f * lnoobj + lcls;

    // Warp reduce -> block reduce -> one plain store per block.
    #pragma unroll
    for (int o = 16; o > 0; o >>= 1)
        v += __shfl_down_sync(0xffffffffu, v, o);

    __shared__ float wsum[THREADS / 32];
    if ((tid & 31) == 0) wsum[tid >> 5] = v;
    __syncthreads();
    if (tid == 0)
        g_part[blockIdx.x] = wsum[0] + wsum[1] + wsum[2] + wsum[3];
}

// Wide finalize: 1024 threads, <=2 float4 loads/thread (all L2-resident),
// short double chains, shuffle tree + 32-leader smem reduce.
__global__ void __launch_bounds__(FIN_THREADS) fin_k(float* __restrict__ out)
{
    const int tid = threadIdx.x;
    const float4* p4 = reinterpret_cast<const float4*>(g_part);

    double acc = 0.0;
    {
        // First slice: tid in [0, 1024) -> indices [0, 1024)
        float4 a = p4[tid];
        acc = ((double)a.x + (double)a.y) + ((double)a.z + (double)a.w);
        // Second slice: indices [1024, 1568)
        const int j = tid + FIN_THREADS;
        if (j < NPART4) {
            float4 b = p4[j];
            acc += ((double)b.x + (double)b.y) + ((double)b.z + (double)b.w);
        }
    }

    #pragma unroll
    for (int o = 16; o > 0; o >>= 1)
        acc += __shfl_down_sync(0xffffffffu, acc, o);

    __shared__ double dsum[FIN_THREADS / 32];
    if ((tid & 31) == 0) dsum[tid >> 5] = acc;
    __syncthreads();

    if (tid < 32) {
        double t = dsum[tid];
        #pragma unroll
        for (int o = 16; o > 0; o >>= 1)
            t += __shfl_down_sync(0xffffffffu, t, o);
        if (tid == 0)
            out[0] = (float)(t * (1.0 / 4096.0));
    }
}

extern "C" void kernel_launch(void* const* d_in, const int* in_sizes, int n_in,
                              void* d_out, int out_size)
{
    const float* pred = (const float*)d_in[0];
    const float* targ = (const float*)d_in[1];
    float* out = (float*)d_out;

    // Max shared carveout so 7 CTAs/SM fit (7 * ~30.8 KB = ~216 KB <= 228 KB).
    cudaFuncSetAttribute(yolo_k,
        cudaFuncAttributePreferredSharedMemoryCarveout,
        cudaSharedmemCarveoutMaxShared);

    yolo_k<<<NBLOCKS, THREADS>>>(pred, targ);
    fin_k<<<1, FIN_THREADS>>>(out);
}

// round 11
// speedup vs baseline: 1.4267x; 1.4267x over previous
#include <cuda_runtime.h>
#include <cstdint>

// YOLOv1 loss, S=14, B=2, C=20, BATCH=4096.
// Kernel 1: per-block cp.async.bulk stage (30 KB) -> compute -> one
//           RED.ADD.F64 to a global accumulator (no fence, no partial array).
// Kernel 2: 1 thread: scale + write scalar, reset accumulator for replay.

constexpr int NCH        = 30;              // 5*B + C
constexpr int NB         = 2;
constexpr int CPB        = 128;             // cells per block (one per thread)
constexpr int THREADS    = 128;
constexpr int TILE_FLTS  = CPB * NCH;       // 3840
constexpr int TILE_BYTES = TILE_FLTS * 4;   // 15360 (16B multiple)
constexpr int NBLOCKS    = 4096 * 14 * 14 / CPB;  // 6272

__device__ double g_acc = 0.0;  // zeroed at load; fin_k re-zeros each replay

__device__ __forceinline__ uint32_t smem_u32(const void* p) {
    return (uint32_t)__cvta_generic_to_shared(p);
}

__global__ void __launch_bounds__(THREADS, 7) yolo_k(
    const float* __restrict__ pred, const float* __restrict__ targ)
{
    __shared__ alignas(16) float sp[TILE_FLTS];
    __shared__ alignas(16) float st_[TILE_FLTS];
    __shared__ alignas(8)  uint64_t mbar;

    const int tid = threadIdx.x;
    const size_t base = (size_t)blockIdx.x * TILE_FLTS;
    const uint32_t mb = smem_u32(&mbar);

    if (tid == 0) {
        asm volatile("mbarrier.init.shared.b64 [%0], 1;" :: "r"(mb) : "memory");
    }
    __syncthreads();

    if (tid == 0) {
        asm volatile("mbarrier.arrive.expect_tx.shared.b64 _, [%0], %1;"
                     :: "r"(mb), "r"(2u * TILE_BYTES) : "memory");
        asm volatile(
            "cp.async.bulk.shared::cta.global.mbarrier::complete_tx::bytes "
            "[%0], [%1], %2, [%3];"
            :: "r"(smem_u32(sp)), "l"(pred + base), "r"((uint32_t)TILE_BYTES),
               "r"(mb) : "memory");
        asm volatile(
            "cp.async.bulk.shared::cta.global.mbarrier::complete_tx::bytes "
            "[%0], [%1], %2, [%3];"
            :: "r"(smem_u32(st_)), "l"(targ + base), "r"((uint32_t)TILE_BYTES),
               "r"(mb) : "memory");
    }

    // Wait for both bulk copies (phase parity 0; block runs one phase only).
    {
        asm volatile(
            "{\n\t"
            ".reg .pred P1;\n\t"
            "WAIT_LOOP_%=:\n\t"
            "mbarrier.try_wait.parity.acquire.cta.shared::cta.b64 P1, [%0], 0, 0x989680;\n\t"
            "@P1 bra.uni WAIT_DONE_%=;\n\t"
            "bra.uni WAIT_LOOP_%=;\n\t"
            "WAIT_DONE_%=:\n\t"
            "}"
            :: "r"(mb) : "memory");
    }

    const float* P = sp  + tid * NCH;
    const float* T = st_ + tid * NCH;

    const float invS = 1.0f / 14.0f;

    const float tobj = T[4];
    const float of = (tobj > 0.0f) ? 1.0f : 0.0f;
    const float nf = 1.0f - of;

    // Target box (box 0 of the tiled pair), in xyxy.
    const float tx0 = T[0] * invS - 0.5f * T[2];
    const float ty0 = T[1] * invS - 0.5f * T[3];
    const float tx1 = T[0] * invS + 0.5f * T[2];
    const float ty1 = T[1] * invS + 0.5f * T[3];
    const float area_t = (tx1 - tx0) * (ty1 - ty0);

    float iou[NB];
    #pragma unroll
    for (int b = 0; b < NB; ++b) {
        const float* Pb = P + 5 * b;
        const float px0 = Pb[0] * invS - 0.5f * Pb[2];
        const float py0 = Pb[1] * invS - 0.5f * Pb[3];
        const float px1 = Pb[0] * invS + 0.5f * Pb[2];
        const float py1 = Pb[1] * invS + 0.5f * Pb[3];
        const float ltx = fmaxf(px0, tx0), lty = fmaxf(py0, ty0);
        const float rbx = fminf(px1, tx1), rby = fminf(py1, ty1);
        const float wx = fmaxf(rbx - ltx, 0.0f);
        const float wy = fmaxf(rby - lty, 0.0f);
        const float inter = wx * wy;
        const float area_p = (px1 - px0) * (py1 - py0);
        iou[b] = inter / (area_p + area_t - inter);  // area_p>0 always
    }
    // jnp.argmax takes the FIRST max -> idx=1 only on strict greater.
    const int idx = (iou[1] > iou[0]) ? 1 : 0;
    const float max_iou = fmaxf(iou[0], iou[1]);

    float lxy = 0.0f, lwh = 0.0f, lobj = 0.0f, lnoobj = 0.0f;
    #pragma unroll
    for (int b = 0; b < NB; ++b) {
        const float* Pb = P + 5 * b;
        const float* Tb = T + 5 * b;
        const bool resp = (of > 0.0f) && (idx == b);
        const float rf = resp ? 1.0f : 0.0f;

        const float dx = Pb[0] - Tb[0];
        const float dy = Pb[1] - Tb[1];
        lxy += rf * (dx * dx + dy * dy);

        const float pw = resp ? Pb[2] : 1.0f;
        const float tw = resp ? Tb[2] : 1.0f;
        const float ph = resp ? Pb[3] : 1.0f;
        const float th = resp ? Tb[3] : 1.0f;
        const float dw = sqrtf(pw) - sqrtf(tw);
        const float dh = sqrtf(ph) - sqrtf(th);
        lwh += rf * (dw * dw + dh * dh);

        const float dob = Pb[4] - max_iou;
        lobj += rf * dob * dob;

        const float dn = Pb[4] - Tb[4];
        lnoobj += dn * dn;
    }
    lnoobj *= nf;

    float lcls = 0.0f;
    #pragma unroll
    for (int k = 10; k < 30; ++k) {
        const float d = P[k] - T[k];
        lcls += d * d;
    }
    lcls *= of;

    float v = 5.0f * (lxy + lwh) + lobj + 0.5f * lnoobj + lcls;

    // Warp reduce -> block reduce -> one RED.ADD.F64 per block.
    #pragma unroll
    for (int o = 16; o > 0; o >>= 1)
        v += __shfl_down_sync(0xffffffffu, v, o);

    __shared__ float wsum[THREADS / 32];
    if ((tid & 31) == 0) wsum[tid >> 5] = v;
    __syncthreads();
    if (tid == 0) {
        const float s = wsum[0] + wsum[1] + wsum[2] + wsum[3];
        atomicAdd(&g_acc, (double)s);   // no return use -> RED.ADD.F64
    }
}

// Minimal finalize: 1 thread. Kernel boundary orders all REDs before this.
__global__ void fin_k(float* __restrict__ out)
{
    out[0] = (float)(g_acc * (1.0 / 4096.0));
    g_acc = 0.0;  // reset for the next graph replay (deterministic)
}

extern "C" void kernel_launch(void* const* d_in, const int* in_sizes, int n_in,
                              void* d_out, int out_size)
{
    const float* pred = (const float*)d_in[0];
    const float* targ = (const float*)d_in[1];
    float* out = (float*)d_out;

    // Max shared carveout so 7 CTAs/SM fit (7 * ~30.8 KB = ~216 KB <= 228 KB).
    cudaFuncSetAttribute(yolo_k,
        cudaFuncAttributePreferredSharedMemoryCarveout,
        cudaSharedmemCarveoutMaxShared);

    yolo_k<<<NBLOCKS, THREADS>>>(pred, targ);
    fin_k<<<1, 1>>>(out);
}

// round 12
// speedup vs baseline: 1.4308x; 1.0029x over previous
#include <cuda_runtime.h>
#include <cstdint>

// YOLOv1 loss, S=14, B=2, C=20, BATCH=4096.
// Kernel 1: per-block cp.async.bulk stage (30 KB) -> compute -> one
//           RED.ADD.F64 to a global accumulator -> griddepcontrol trigger.
// Kernel 2 (PDL): griddepcontrol.wait -> scale + write scalar + reset acc.
//           Launched with programmatic stream serialization so its launch
//           latency hides under kernel 1's execution.

constexpr int NCH        = 30;              // 5*B + C
constexpr int NB         = 2;
constexpr int CPB        = 128;             // cells per block (one per thread)
constexpr int THREADS    = 128;
constexpr int TILE_FLTS  = CPB * NCH;       // 3840
constexpr int TILE_BYTES = TILE_FLTS * 4;   // 15360 (16B multiple)
constexpr int NBLOCKS    = 4096 * 14 * 14 / CPB;  // 6272

__device__ double g_acc = 0.0;  // zeroed at load; fin_k re-zeros each replay

__device__ __forceinline__ uint32_t smem_u32(const void* p) {
    return (uint32_t)__cvta_generic_to_shared(p);
}

__global__ void __launch_bounds__(THREADS, 7) yolo_k(
    const float* __restrict__ pred, const float* __restrict__ targ)
{
    __shared__ alignas(16) float sp[TILE_FLTS];
    __shared__ alignas(16) float st_[TILE_FLTS];
    __shared__ alignas(8)  uint64_t mbar;

    const int tid = threadIdx.x;
    const size_t base = (size_t)blockIdx.x * TILE_FLTS;
    const uint32_t mb = smem_u32(&mbar);

    if (tid == 0) {
        asm volatile("mbarrier.init.shared.b64 [%0], 1;" :: "r"(mb) : "memory");
    }
    __syncthreads();

    if (tid == 0) {
        asm volatile("mbarrier.arrive.expect_tx.shared.b64 _, [%0], %1;"
                     :: "r"(mb), "r"(2u * TILE_BYTES) : "memory");
        asm volatile(
            "cp.async.bulk.shared::cta.global.mbarrier::complete_tx::bytes "
            "[%0], [%1], %2, [%3];"
            :: "r"(smem_u32(sp)), "l"(pred + base), "r"((uint32_t)TILE_BYTES),
               "r"(mb) : "memory");
        asm volatile(
            "cp.async.bulk.shared::cta.global.mbarrier::complete_tx::bytes "
            "[%0], [%1], %2, [%3];"
            :: "r"(smem_u32(st_)), "l"(targ + base), "r"((uint32_t)TILE_BYTES),
               "r"(mb) : "memory");
    }

    // Wait for both bulk copies (phase parity 0; block runs one phase only).
    {
        asm volatile(
            "{\n\t"
            ".reg .pred P1;\n\t"
            "WAIT_LOOP_%=:\n\t"
            "mbarrier.try_wait.parity.acquire.cta.shared::cta.b64 P1, [%0], 0, 0x989680;\n\t"
            "@P1 bra.uni WAIT_DONE_%=;\n\t"
            "bra.uni WAIT_LOOP_%=;\n\t"
            "WAIT_DONE_%=:\n\t"
            "}"
            :: "r"(mb) : "memory");
    }

    const float* P = sp  + tid * NCH;
    const float* T = st_ + tid * NCH;

    const float invS = 1.0f / 14.0f;

    const float tobj = T[4];
    const float of = (tobj > 0.0f) ? 1.0f : 0.0f;
    const float nf = 1.0f - of;

    // Target box (box 0 of the tiled pair), in xyxy.
    const float tx0 = T[0] * invS - 0.5f * T[2];
    const float ty0 = T[1] * invS - 0.5f * T[3];
    const float tx1 = T[0] * invS + 0.5f * T[2];
    const float ty1 = T[1] * invS + 0.5f * T[3];
    const float area_t = (tx1 - tx0) * (ty1 - ty0);

    float iou[NB];
    #pragma unroll
    for (int b = 0; b < NB; ++b) {
        const float* Pb = P + 5 * b;
        const float px0 = Pb[0] * invS - 0.5f * Pb[2];
        const float py0 = Pb[1] * invS - 0.5f * Pb[3];
        const float px1 = Pb[0] * invS + 0.5f * Pb[2];
        const float py1 = Pb[1] * invS + 0.5f * Pb[3];
        const float ltx = fmaxf(px0, tx0), lty = fmaxf(py0, ty0);
        const float rbx = fminf(px1, tx1), rby = fminf(py1, ty1);
        const float wx = fmaxf(rbx - ltx, 0.0f);
        const float wy = fmaxf(rby - lty, 0.0f);
        const float inter = wx * wy;
        const float area_p = (px1 - px0) * (py1 - py0);
        iou[b] = inter / (area_p + area_t - inter);  // area_p>0 always
    }
    // jnp.argmax takes the FIRST max -> idx=1 only on strict greater.
    const int idx = (iou[1] > iou[0]) ? 1 : 0;
    const float max_iou = fmaxf(iou[0], iou[1]);

    float lxy = 0.0f, lwh = 0.0f, lobj = 0.0f, lnoobj = 0.0f;
    #pragma unroll
    for (int b = 0; b < NB; ++b) {
        const float* Pb = P + 5 * b;
        const float* Tb = T + 5 * b;
        const bool resp = (of > 0.0f) && (idx == b);
        const float rf = resp ? 1.0f : 0.0f;

        const float dx = Pb[0] - Tb[0];
        const float dy = Pb[1] - Tb[1];
        lxy += rf * (dx * dx + dy * dy);

        const float pw = resp ? Pb[2] : 1.0f;
        const float tw = resp ? Tb[2] : 1.0f;
        const float ph = resp ? Pb[3] : 1.0f;
        const float th = resp ? Tb[3] : 1.0f;
        const float dw = sqrtf(pw) - sqrtf(tw);
        const float dh = sqrtf(ph) - sqrtf(th);
        lwh += rf * (dw * dw + dh * dh);

        const float dob = Pb[4] - max_iou;
        lobj += rf * dob * dob;

        const float dn = Pb[4] - Tb[4];
        lnoobj += dn * dn;
    }
    lnoobj *= nf;

    float lcls = 0.0f;
    #pragma unroll
    for (int k = 10; k < 30; ++k) {
        const float d = P[k] - T[k];
        lcls += d * d;
    }
    lcls *= of;

    float v = 5.0f * (lxy + lwh) + lobj + 0.5f * lnoobj + lcls;

    // Warp reduce -> block reduce -> one RED.ADD.F64 per block.
    #pragma unroll
    for (int o = 16; o > 0; o >>= 1)
        v += __shfl_down_sync(0xffffffffu, v, o);

    __shared__ float wsum[THREADS / 32];
    if ((tid & 31) == 0) wsum[tid >> 5] = v;
    __syncthreads();
    if (tid == 0) {
        const float s = wsum[0] + wsum[1] + wsum[2] + wsum[3];
        atomicAdd(&g_acc, (double)s);   // no return use -> RED.ADD.F64
    }

    // PDL trigger: all memory ops issued before this (incl. tid0's RED,
    // ordered by the syncthreads above for other threads' view... the RED is
    // issued by tid0 before its own trigger, which is the guarantee that
    // matters) are visible to the dependent grid after its griddepcontrol.wait.
    asm volatile("griddepcontrol.launch_dependents;" ::: "memory");
}

// Finalize, launched with programmatic stream serialization (PDL): its launch
// overlaps yolo_k; griddepcontrol.wait releases once yolo_k's grid completes
// its triggers, with memory visibility of all pre-trigger writes.
__global__ void fin_k(float* __restrict__ out)
{
    asm volatile("griddepcontrol.wait;" ::: "memory");
    out[0] = (float)(g_acc * (1.0 / 4096.0));
    g_acc = 0.0;  // reset for the next graph replay (deterministic)
}

extern "C" void kernel_launch(void* const* d_in, const int* in_sizes, int n_in,
                              void* d_out, int out_size)
{
    const float* pred = (const float*)d_in[0];
    const float* targ = (const float*)d_in[1];
    float* out = (float*)d_out;

    // Max shared carveout so 7 CTAs/SM fit (7 * ~30.8 KB = ~216 KB <= 228 KB).
    cudaFuncSetAttribute(yolo_k,
        cudaFuncAttributePreferredSharedMemoryCarveout,
        cudaSharedmemCarveoutMaxShared);

    yolo_k<<<NBLOCKS, THREADS>>>(pred, targ);

    // fin_k with PDL: launch latency hides under yolo_k.
    cudaLaunchAttribute attrs[1];
    attrs[0].id = cudaLaunchAttributeProgrammaticStreamSerialization;
    attrs[0].val.programmaticStreamSerializationAllowed = 1;
    cudaLaunchConfig_t cfg = {};
    cfg.gridDim  = dim3(1, 1, 1);
    cfg.blockDim = dim3(1, 1, 1);
    cfg.dynamicSmemBytes = 0;
    cfg.stream = 0;
    cfg.attrs = attrs;
    cfg.numAttrs = 1;
    cudaLaunchKernelEx(&cfg, fin_k, out);
}